// round 13
// baseline (speedup 1.0000x reference)
#include <cuda_runtime.h>

// Problem constants
#define BB 4
#define CC 8
#define NN 1024
#define DD 256
#define BN (BB*NN)          // 4096
#define BCN (BB*CC*NN)      // 32768
#define MAXI 17
#define SCALEF 0.0625f      // D^-0.5 = 1/16

// ---------------- scratch (static device arrays; no allocs) ----------------
__device__ float g_q[BB*CC*NN*DD];          // 32 MB  [(b*C+c)*N+n][d]
__device__ float g_k[BB*CC*NN*DD];          // 32 MB
__device__ float g_S[33554432];             // 128 MB scaled logits [(bc*N+n)*N+m]
__device__ float g_rowmax[BCN];
__device__ float g_invZ[BCN];
__device__ float g_sum_edge[BN*NN];         // 16 MB
__device__ int   g_idx[BN*MAXI];
__device__ int   g_cnt[BN];
__device__ float g_nr[BCN*MAXI];            // normalized row values (masked attn / rowsum)
__device__ float g_colsum[BCN];
__device__ float g_invcol[BCN];
__device__ int   g_colcnt[BN];              // CSC per batch (mask same for all channels)
__device__ int   g_colent[BN*NN];           // 16 MB packed (n<<5 | j)

// ---------------- K1: qk = x @ W, scatter into g_q / g_k -------------------
// x [4096,256], W [256,4096]; out col j -> (s=j>>11, c=(j>>8)&7, d=j&255)
__global__ void k1_proj(const float* __restrict__ x, const float* __restrict__ W) {
    __shared__ float As[16][132];   // transposed A: As[kk][row]
    __shared__ float Bs[16][132];   // Bs[kk][col]
    const int m0 = blockIdx.y * 128, n0 = blockIdx.x * 128;
    const int tid = threadIdx.x;
    const int tx = tid & 15, ty = tid >> 4;
    float acc[8][8];
    #pragma unroll
    for (int i = 0; i < 8; i++)
        #pragma unroll
        for (int j = 0; j < 8; j++) acc[i][j] = 0.f;

    for (int k0 = 0; k0 < DD; k0 += 16) {
        #pragma unroll
        for (int i = 0; i < 2; i++) {            // A: 128 rows x 16 k, transpose
            int idx = tid + i * 256;
            int row = idx >> 2, vc = idx & 3;
            float4 v = *(const float4*)&x[(m0 + row) * DD + k0 + vc * 4];
            As[vc*4+0][row] = v.x; As[vc*4+1][row] = v.y;
            As[vc*4+2][row] = v.z; As[vc*4+3][row] = v.w;
        }
        #pragma unroll
        for (int i = 0; i < 2; i++) {            // B: 16 k rows x 128 cols, direct
            int idx = tid + i * 256;
            int kr = idx >> 5, vc = idx & 31;
            *(float4*)&Bs[kr][vc*4] = *(const float4*)&W[(k0 + kr) * 4096 + n0 + vc * 4];
        }
        __syncthreads();
        #pragma unroll
        for (int kk = 0; kk < 16; kk++) {
            float a[8], bb[8];
            *(float4*)&a[0]  = *(float4*)&As[kk][ty*8];
            *(float4*)&a[4]  = *(float4*)&As[kk][ty*8+4];
            *(float4*)&bb[0] = *(float4*)&Bs[kk][tx*8];
            *(float4*)&bb[4] = *(float4*)&Bs[kk][tx*8+4];
            #pragma unroll
            for (int i = 0; i < 8; i++)
                #pragma unroll
                for (int j = 0; j < 8; j++) acc[i][j] += a[i] * bb[j];
        }
        __syncthreads();
    }
    #pragma unroll
    for (int i = 0; i < 8; i++) {
        int m = m0 + ty*8 + i;
        int b = m >> 10, n = m & 1023;
        #pragma unroll
        for (int j = 0; j < 8; j++) {
            int col = n0 + tx*8 + j;
            int s = col >> 11, c = (col >> 8) & 7, d = col & 255;
            float* dst = s ? g_k : g_q;
            dst[((b*CC + c)*NN + n) * DD + d] = acc[i][j];
        }
    }
}

// ---------------- K2: S = scale * q @ k^T per (b,c) ------------------------
__global__ void k2_qkT(void) {
    __shared__ float As[16][132];
    __shared__ float Bs[16][132];
    const int bc = blockIdx.z;
    const float* qp = g_q + (size_t)bc * NN * DD;
    const float* kp = g_k + (size_t)bc * NN * DD;
    float* Sout = g_S + (size_t)bc * NN * NN;
    const int n0 = blockIdx.y * 128, m0 = blockIdx.x * 128;
    const int tid = threadIdx.x;
    const int tx = tid & 15, ty = tid >> 4;
    float acc[8][8];
    #pragma unroll
    for (int i = 0; i < 8; i++)
        #pragma unroll
        for (int j = 0; j < 8; j++) acc[i][j] = 0.f;

    for (int k0 = 0; k0 < DD; k0 += 16) {
        #pragma unroll
        for (int i = 0; i < 2; i++) {
            int idx = tid + i * 256;
            int row = idx >> 2, vc = idx & 3;
            float4 v = *(const float4*)&qp[(n0 + row) * DD + k0 + vc * 4];
            As[vc*4+0][row] = v.x; As[vc*4+1][row] = v.y;
            As[vc*4+2][row] = v.z; As[vc*4+3][row] = v.w;
        }
        #pragma unroll
        for (int i = 0; i < 2; i++) {
            int idx = tid + i * 256;
            int row = idx >> 2, vc = idx & 3;
            float4 v = *(const float4*)&kp[(m0 + row) * DD + k0 + vc * 4];
            Bs[vc*4+0][row] = v.x; Bs[vc*4+1][row] = v.y;
            Bs[vc*4+2][row] = v.z; Bs[vc*4+3][row] = v.w;
        }
        __syncthreads();
        #pragma unroll
        for (int kk = 0; kk < 16; kk++) {
            float a[8], bb[8];
            *(float4*)&a[0]  = *(float4*)&As[kk][ty*8];
            *(float4*)&a[4]  = *(float4*)&As[kk][ty*8+4];
            *(float4*)&bb[0] = *(float4*)&Bs[kk][tx*8];
            *(float4*)&bb[4] = *(float4*)&Bs[kk][tx*8+4];
            #pragma unroll
            for (int i = 0; i < 8; i++)
                #pragma unroll
                for (int j = 0; j < 8; j++) acc[i][j] += a[i] * bb[j];
        }
        __syncthreads();
    }
    #pragma unroll
    for (int i = 0; i < 8; i++) {
        int nrow = n0 + ty*8 + i;
        float4 o0, o1;
        o0.x = acc[i][0]*SCALEF; o0.y = acc[i][1]*SCALEF;
        o0.z = acc[i][2]*SCALEF; o0.w = acc[i][3]*SCALEF;
        o1.x = acc[i][4]*SCALEF; o1.y = acc[i][5]*SCALEF;
        o1.z = acc[i][6]*SCALEF; o1.w = acc[i][7]*SCALEF;
        *(float4*)&Sout[(size_t)nrow * NN + m0 + tx*8]     = o0;
        *(float4*)&Sout[(size_t)nrow * NN + m0 + tx*8 + 4] = o1;
    }
}

// ---------------- K3: per-row softmax stats + channel-summed sum_edge ------
// one block per (b,n); 256 threads, each owns 4 contiguous columns
__global__ void k3_stats(void) {
    __shared__ float red[32];
    const int bn = blockIdx.x;
    const int b = bn >> 10, n = bn & 1023;
    const int tid = threadIdx.x;
    const int lane = tid & 31, wid = tid >> 5;

    if (tid == 0) g_colcnt[bn] = 0;                       // zero CSC counters
    if (tid < CC) g_colsum[(b*CC + tid)*NN + n] = 0.f;    // zero colsums

    float4 srw = make_float4(0.f, 0.f, 0.f, 0.f);
    for (int c = 0; c < CC; c++) {
        const float* Srow = g_S + (size_t)((b*CC + c)*NN + n) * NN;
        float4 v = ((const float4*)Srow)[tid];
        // max
        float lm = fmaxf(fmaxf(v.x, v.y), fmaxf(v.z, v.w));
        #pragma unroll
        for (int off = 16; off; off >>= 1)
            lm = fmaxf(lm, __shfl_xor_sync(0xffffffffu, lm, off));
        if (lane == 0) red[wid] = lm;
        __syncthreads();
        if (tid < 32) {
            float t = (tid < 8) ? red[tid] : -3.4e38f;
            #pragma unroll
            for (int off = 4; off; off >>= 1)
                t = fmaxf(t, __shfl_xor_sync(0xffffffffu, t, off));
            if (tid == 0) red[0] = t;
        }
        __syncthreads();
        float mx = red[0];
        __syncthreads();
        // exp + sum
        float4 e;
        e.x = __expf(v.x - mx); e.y = __expf(v.y - mx);
        e.z = __expf(v.z - mx); e.w = __expf(v.w - mx);
        float ls = e.x + e.y + e.z + e.w;
        #pragma unroll
        for (int off = 16; off; off >>= 1)
            ls += __shfl_xor_sync(0xffffffffu, ls, off);
        if (lane == 0) red[wid] = ls;
        __syncthreads();
        if (tid < 32) {
            float t = (tid < 8) ? red[tid] : 0.f;
            #pragma unroll
            for (int off = 4; off; off >>= 1)
                t += __shfl_xor_sync(0xffffffffu, t, off);
            if (tid == 0) red[0] = t;
        }
        __syncthreads();
        float Z = red[0];
        float invZ = 1.0f / Z;
        if (tid == 0) {
            g_rowmax[(b*CC + c)*NN + n] = mx;
            g_invZ[(b*CC + c)*NN + n]   = invZ;
        }
        srw.x += e.x * invZ; srw.y += e.y * invZ;
        srw.z += e.z * invZ; srw.w += e.w * invZ;
        __syncthreads();
    }
    ((float4*)&g_sum_edge[(size_t)bn * NN])[tid] = srw;
}

// ---------------- K4: top-16 (+diag) per (b,n) via iterative argmax --------
__global__ void k4_topk(void) {
    __shared__ float buf[NN];
    __shared__ float rv[8];
    __shared__ int   ri[8];
    __shared__ int   sel[MAXI];
    const int bn = blockIdx.x;
    const int n = bn & 1023;
    const int tid = threadIdx.x;
    const int lane = tid & 31, wid = tid >> 5;
    ((float4*)buf)[tid] = ((const float4*)&g_sum_edge[(size_t)bn * NN])[tid];
    __syncthreads();
    for (int it = 0; it < 16; it++) {
        int base = tid * 4;
        float bv = buf[base]; int bi = base;
        #pragma unroll
        for (int q = 1; q < 4; q++) {
            float v = buf[base + q];
            if (v > bv) { bv = v; bi = base + q; }   // strict > keeps lowest index on tie
        }
        #pragma unroll
        for (int off = 16; off; off >>= 1) {
            float ov = __shfl_xor_sync(0xffffffffu, bv, off);
            int   oi = __shfl_xor_sync(0xffffffffu, bi, off);
            if (ov > bv || (ov == bv && oi < bi)) { bv = ov; bi = oi; }
        }
        if (lane == 0) { rv[wid] = bv; ri[wid] = bi; }
        __syncthreads();
        if (tid == 0) {
            float fv = rv[0]; int fi = ri[0];
            for (int w = 1; w < 8; w++)
                if (rv[w] > fv || (rv[w] == fv && ri[w] < fi)) { fv = rv[w]; fi = ri[w]; }
            sel[it] = fi;
            buf[fi] = -3.4e38f;
        }
        __syncthreads();
    }
    if (tid == 0) {
        int cnt = 16;
        bool has = false;
        for (int j = 0; j < 16; j++) if (sel[j] == n) has = true;
        if (!has) { sel[16] = n; cnt = 17; }
        g_cnt[bn] = cnt;
        for (int j = 0; j < cnt; j++) g_idx[bn*MAXI + j] = sel[j];
    }
}

// ---------------- K5: gather attn at mask, row-normalize, colsums, CSC -----
__global__ void k5_gather(void) {
    int gid = blockIdx.x * blockDim.x + threadIdx.x;   // (bc*N + n)
    if (gid >= BCN) return;
    int bc = gid >> 10, n = gid & 1023;
    int b = bc >> 3, c = bc & 7;
    int bn = b*NN + n;
    int cnt = g_cnt[bn];
    float mx = g_rowmax[gid], iZ = g_invZ[gid];
    const float* Srow = g_S + (size_t)gid * NN;
    float a[MAXI]; int id[MAXI];
    float rs = 0.f;
    #pragma unroll
    for (int j = 0; j < MAXI; j++) {
        a[j] = 0.f; id[j] = 0;
        if (j < cnt) {
            int m = g_idx[bn*MAXI + j];
            id[j] = m;
            float e = __expf(Srow[m] - mx) * iZ;
            a[j] = e; rs += e;
        }
    }
    float inv = 1.0f / (rs + 1e-6f);
    #pragma unroll
    for (int j = 0; j < MAXI; j++) {
        if (j < cnt) {
            float nr = a[j] * inv;
            g_nr[gid*MAXI + j] = nr;
            atomicAdd(&g_colsum[bc*NN + id[j]], nr);
            if (c == 0) {   // mask identical across channels: build CSC once per b
                int p = atomicAdd(&g_colcnt[b*NN + id[j]], 1);
                g_colent[(b*NN + id[j])*NN + p] = (n << 5) | j;
            }
        }
    }
}

// ---------------- K5b: invert column sums ----------------------------------
__global__ void k5b_invcol(void) {
    int gid = blockIdx.x * blockDim.x + threadIdx.x;
    if (gid < BCN) g_invcol[gid] = 1.0f / (g_colsum[gid] + 1e-6f);
}

// ---------------- K6: out = norm_row @ norm_col^T (sparse x sparse) --------
// one block per (b,c,n): dense 1024-wide output row assembled in smem
__global__ void k6_final(float* __restrict__ out) {
    __shared__ float row[NN];
    const int bcn = blockIdx.x;
    const int bc = bcn >> 10, n = bcn & 1023;
    const int b = bc >> 3;
    const int tid = threadIdx.x;    // 128
    #pragma unroll
    for (int i = 0; i < 2; i++)
        ((float4*)row)[tid + i*128] = make_float4(0.f, 0.f, 0.f, 0.f);
    __syncthreads();
    const int bn = b*NN + n;
    const int cnt = g_cnt[bn];
    for (int j = 0; j < cnt; j++) {
        int k = g_idx[bn*MAXI + j];
        float ai = g_nr[(size_t)bcn*MAXI + j] * g_invcol[bc*NN + k];
        int cc = g_colcnt[b*NN + k];
        const int* ent = &g_colent[(b*NN + k)*NN];
        for (int e = tid; e < cc; e += 128) {
            int pk = ent[e];
            int m = pk >> 5, j2 = pk & 31;
            float ncv = g_nr[(bc*NN + m)*MAXI + j2];
            atomicAdd(&row[m], ai * ncv);
        }
    }
    __syncthreads();
    float* orow = out + (size_t)bcn * NN;
    #pragma unroll
    for (int i = 0; i < 2; i++)
        ((float4*)orow)[tid + i*128] = ((float4*)row)[tid + i*128];
}

// ---------------- launch ----------------------------------------------------
extern "C" void kernel_launch(void* const* d_in, const int* in_sizes, int n_in,
                              void* d_out, int out_size) {
    const float* x = (const float*)d_in[0];     // [4,1024,256]
    const float* W = (const float*)d_in[1];     // [256,4096]
    float* out = (float*)d_out;                 // [4,8,1024,1024]

    k1_proj<<<dim3(32, 32), 256>>>(x, W);
    k2_qkT<<<dim3(8, 8, 32), 256>>>();
    k3_stats<<<BN, 256>>>();
    k4_topk<<<BN, 256>>>();
    k5_gather<<<BCN / 256, 256>>>();
    k5b_invcol<<<BCN / 256, 256>>>();
    k6_final<<<BCN, 128>>>(out);
}

// round 15
// speedup vs baseline: 1.0615x; 1.0615x over previous
#include <cuda_runtime.h>
#include <cuda_bf16.h>
#include <cstdint>

// Problem constants
#define BB 4
#define CC 8
#define NN 1024
#define DD 256
#define BN (BB*NN)          // 4096
#define BCN (BB*CC*NN)      // 32768
#define MAXI 17
#define SCALEF 0.0625f      // D^-0.5 = 1/16

// ---------------- scratch (static device arrays; no allocs) ----------------
__device__ __align__(256) __nv_bfloat16 gx_h[BN*DD], gx_m[BN*DD], gx_l[BN*DD];    // x splits [4096][256]
__device__ __align__(256) __nv_bfloat16 gW_h[BN*DD], gW_m[BN*DD], gW_l[BN*DD];    // W^T splits [4096][256]
__device__ __align__(256) __nv_bfloat16 gq_h[BCN*DD], gq_m[BCN*DD], gq_l[BCN*DD]; // q splits
__device__ __align__(256) __nv_bfloat16 gk_h[BCN*DD], gk_m[BCN*DD], gk_l[BCN*DD]; // k splits

__device__ float g_S[33554432];             // 128 MB scaled logits
__device__ float g_rowmax[BCN];
__device__ float g_invZ[BCN];
__device__ float g_sum_edge[BN*NN];
__device__ int   g_idx[BN*MAXI];
__device__ int   g_cnt[BN];
__device__ float g_nr[BCN*MAXI];
__device__ float g_colsum[BCN];
__device__ float g_invcol[BCN];
__device__ int   g_colcnt[BN];
__device__ int   g_colent[BN*NN];

// ---------------- mma.sync helpers (sm_80+ features; valid on plain sm_103) -
#define LDSM4(r0,r1,r2,r3,addr) \
    asm volatile("ldmatrix.sync.aligned.m8n8.x4.shared.b16 {%0,%1,%2,%3}, [%4];" \
                 : "=r"(r0), "=r"(r1), "=r"(r2), "=r"(r3) : "r"(addr))

#define MMA16816(d, a, b0, b1) \
    asm volatile("mma.sync.aligned.m16n8k16.row.col.f32.bf16.bf16.f32 " \
                 "{%0,%1,%2,%3}, {%4,%5,%6,%7}, {%8,%9}, {%0,%1,%2,%3};" \
                 : "+f"((d)[0]), "+f"((d)[1]), "+f"((d)[2]), "+f"((d)[3]) \
                 : "r"((a)[0]), "r"((a)[1]), "r"((a)[2]), "r"((a)[3]), "r"(b0), "r"(b1))

__device__ __forceinline__ uint32_t smem_u32(const void* p) {
    uint32_t a;
    asm("{ .reg .u64 t; cvta.to.shared.u64 t, %1; cvt.u32.u64 %0, t; }" : "=r"(a) : "l"(p));
    return a;
}

// Fill one [128 rows x 64 bf16] SW128-swizzled smem tile from src rows (512B stride)
__device__ __forceinline__ void fill_tile(__nv_bfloat16* dst, const __nv_bfloat16* src,
                                          int row0, int kc, int tid) {
    const char* s = (const char*)src + (size_t)row0 * 512 + kc * 128;
    char* d = (char*)dst;
    #pragma unroll
    for (int i = 0; i < 4; i++) {
        int idx = tid + i * 256;           // 0..1023 (128 rows x 8 segs)
        int r = idx >> 3, seg = idx & 7;
        float4 v = *(const float4*)(s + (size_t)r * 512 + seg * 16);
        int off = r * 128 + seg * 16;
        *(float4*)(d + (off ^ ((off >> 3) & 0x70))) = v;
    }
}

__device__ __forceinline__ void split3(float v, __nv_bfloat16& h, __nv_bfloat16& m, __nv_bfloat16& l) {
    h = __float2bfloat16(v);
    float r1 = v - __bfloat162float(h);
    m = __float2bfloat16(r1);
    float r2 = r1 - __bfloat162float(m);
    l = __float2bfloat16(r2);
}

// ---------------- K0a: split x into bf16 hi/mid/lo --------------------------
__global__ void k0_splitx(const float* __restrict__ x) {
    int i = blockIdx.x * 256 + threadIdx.x;
    float v = x[i];
    __nv_bfloat16 h, m, l;
    split3(v, h, m, l);
    gx_h[i] = h; gx_m[i] = m; gx_l[i] = l;
}

// ---------------- K0b: transpose W [256][4096] -> W^T splits [4096][256] ----
__global__ void k0_splitW(const float* __restrict__ W) {
    __shared__ float t[32][33];
    int j0 = blockIdx.x * 32, k0 = blockIdx.y * 32;
    int tx = threadIdx.x, ty = threadIdx.y;     // (32,8)
    #pragma unroll
    for (int i = 0; i < 4; i++)
        t[ty + i * 8][tx] = W[(size_t)(k0 + ty + i * 8) * 4096 + j0 + tx];
    __syncthreads();
    #pragma unroll
    for (int i = 0; i < 4; i++) {
        int j = j0 + ty + i * 8;
        float v = t[tx][ty + i * 8];
        __nv_bfloat16 h, m, l;
        split3(v, h, m, l);
        size_t o = (size_t)j * 256 + k0 + tx;
        gW_h[o] = h; gW_m[o] = m; gW_l[o] = l;
    }
}

// ======================= shared mainloop (macro-free inline) ================
// 8 warps; warp tile 64(m) x 32(n); block tile 128x128; K-chunk 64.
// acc[mi][ni][e]; 6 split-term passes x 4 k-chunks = 24 tile iterations.
struct MmaCtx {
    uint32_t sA, sB;
    int wm, wn, lane;
};

__device__ __forceinline__ void mma_chunk(const MmaCtx& cx, float acc[4][4][4]) {
    #pragma unroll
    for (int kk = 0; kk < 4; kk++) {
        const int kb = kk * 32 + (cx.lane >> 4) * 16;  // byte offset in 128B row
        uint32_t a[4][4];
        #pragma unroll
        for (int mi = 0; mi < 4; mi++) {
            int row = cx.wm + mi * 16 + (cx.lane & 15);
            int off = row * 128 + kb;
            LDSM4(a[mi][0], a[mi][1], a[mi][2], a[mi][3],
                  cx.sA + (off ^ ((off >> 3) & 0x70)));
        }
        uint32_t b[2][4];
        #pragma unroll
        for (int nj = 0; nj < 2; nj++) {
            int row = cx.wn + nj * 16 + (cx.lane & 15);
            int off = row * 128 + kb;
            LDSM4(b[nj][0], b[nj][1], b[nj][2], b[nj][3],
                  cx.sB + (off ^ ((off >> 3) & 0x70)));
        }
        #pragma unroll
        for (int mi = 0; mi < 4; mi++)
            #pragma unroll
            for (int ni = 0; ni < 4; ni++)
                MMA16816(acc[mi][ni], a[mi], b[ni >> 1][ni & 1], b[ni >> 1][(ni & 1) + 2]);
    }
}

// ---------------- K1: y = x @ W (6-term bf16 split), split epilogue --------
__global__ void __launch_bounds__(256, 2) k1_mma() {
    __shared__ __align__(128) __nv_bfloat16 sA[128*64];
    __shared__ __align__(128) __nv_bfloat16 sB[128*64];
    const int tid = threadIdx.x, wid = tid >> 5, lane = tid & 31;
    MmaCtx cx{smem_u32(sA), smem_u32(sB), (wid & 1) * 64, (wid >> 1) * 32, lane};

    const int m0 = blockIdx.y * 128;   // token rows
    const int n0 = blockIdx.x * 128;   // output cols

    float acc[4][4][4];
    #pragma unroll
    for (int mi = 0; mi < 4; mi++)
        #pragma unroll
        for (int ni = 0; ni < 4; ni++)
            #pragma unroll
            for (int e = 0; e < 4; e++) acc[mi][ni][e] = 0.f;

    for (int g = 0; g < 6; g++) {
        const __nv_bfloat16 *pa, *pb;
        switch (g) {
            case 0: pa = gx_h; pb = gW_h; break;
            case 1: pa = gx_h; pb = gW_m; break;
            case 2: pa = gx_m; pb = gW_h; break;
            case 3: pa = gx_h; pb = gW_l; break;
            case 4: pa = gx_m; pb = gW_m; break;
            default: pa = gx_l; pb = gW_h; break;
        }
        for (int kc = 0; kc < 4; kc++) {
            fill_tile(sA, pa, m0, kc, tid);
            fill_tile(sB, pb, n0, kc, tid);
            __syncthreads();
            mma_chunk(cx, acc);
            __syncthreads();
        }
    }

    // epilogue: split y -> q/k bf16 hi/mid/lo (in-place residual on acc)
    const int s = n0 >> 11, c = (n0 >> 8) & 7, d0 = (n0 & 255) + cx.wn;
    __nv_bfloat16* const dsts[3] = { s ? gk_h : gq_h, s ? gk_m : gq_m, s ? gk_l : gq_l };
    #pragma unroll
    for (int sp = 0; sp < 3; sp++) {
        __nv_bfloat16* dst = dsts[sp];
        #pragma unroll
        for (int mi = 0; mi < 4; mi++) {
            #pragma unroll
            for (int half = 0; half < 2; half++) {
                int row = m0 + cx.wm + mi * 16 + (lane >> 2) + half * 8;   // token
                int b = row >> 10, n = row & 1023;
                size_t base = ((size_t)(b * CC + c) * NN + n) * DD + d0;
                #pragma unroll
                for (int ni = 0; ni < 4; ni++) {
                    float v0 = acc[mi][ni][half * 2 + 0];
                    float v1 = acc[mi][ni][half * 2 + 1];
                    __nv_bfloat16 h0 = __float2bfloat16(v0);
                    __nv_bfloat16 h1 = __float2bfloat16(v1);
                    __nv_bfloat162 p; p.x = h0; p.y = h1;
                    *(__nv_bfloat162*)&dst[base + ni * 8 + (lane & 3) * 2] = p;
                    acc[mi][ni][half * 2 + 0] = v0 - __bfloat162float(h0);
                    acc[mi][ni][half * 2 + 1] = v1 - __bfloat162float(h1);
                }
            }
        }
    }
}

// ---------------- K2: S = scale * q @ k^T (6-term bf16 split) ---------------
__global__ void __launch_bounds__(256, 2) k2_mma() {
    __shared__ __align__(128) __nv_bfloat16 sA[128*64];
    __shared__ __align__(128) __nv_bfloat16 sB[128*64];
    const int tid = threadIdx.x, wid = tid >> 5, lane = tid & 31;
    MmaCtx cx{smem_u32(sA), smem_u32(sB), (wid & 1) * 64, (wid >> 1) * 32, lane};

    const int bc = blockIdx.z;
    const int rowA0 = bc * NN + blockIdx.y * 128;   // q rows -> S rows
    const int rowB0 = bc * NN + blockIdx.x * 128;   // k rows -> S cols
    const int m0 = blockIdx.x * 128;

    float acc[4][4][4];
    #pragma unroll
    for (int mi = 0; mi < 4; mi++)
        #pragma unroll
        for (int ni = 0; ni < 4; ni++)
            #pragma unroll
            for (int e = 0; e < 4; e++) acc[mi][ni][e] = 0.f;

    for (int g = 0; g < 6; g++) {
        const __nv_bfloat16 *pa, *pb;
        switch (g) {
            case 0: pa = gq_h; pb = gk_h; break;
            case 1: pa = gq_h; pb = gk_m; break;
            case 2: pa = gq_m; pb = gk_h; break;
            case 3: pa = gq_h; pb = gk_l; break;
            case 4: pa = gq_m; pb = gk_m; break;
            default: pa = gq_l; pb = gk_h; break;
        }
        for (int kc = 0; kc < 4; kc++) {
            fill_tile(sA, pa, rowA0, kc, tid);
            fill_tile(sB, pb, rowB0, kc, tid);
            __syncthreads();
            mma_chunk(cx, acc);
            __syncthreads();
        }
    }

    // epilogue: scale & store fp32 logits (coalesced float2)
    #pragma unroll
    for (int mi = 0; mi < 4; mi++) {
        #pragma unroll
        for (int half = 0; half < 2; half++) {
            int srow = blockIdx.y * 128 + cx.wm + mi * 16 + (lane >> 2) + half * 8;
            float* Sr = g_S + ((size_t)bc * NN + srow) * NN + m0 + cx.wn;
            #pragma unroll
            for (int ni = 0; ni < 4; ni++) {
                float2 v;
                v.x = acc[mi][ni][half * 2 + 0] * SCALEF;
                v.y = acc[mi][ni][half * 2 + 1] * SCALEF;
                *(float2*)&Sr[ni * 8 + (lane & 3) * 2] = v;
            }
        }
    }
}

// ---------------- K3: per-row softmax stats + channel-summed sum_edge ------
__global__ void k3_stats(void) {
    __shared__ float red[32];
    const int bn = blockIdx.x;
    const int b = bn >> 10, n = bn & 1023;
    const int tid = threadIdx.x;
    const int lane = tid & 31, wid = tid >> 5;

    if (tid == 0) g_colcnt[bn] = 0;
    if (tid < CC) g_colsum[(b*CC + tid)*NN + n] = 0.f;

    float4 srw = make_float4(0.f, 0.f, 0.f, 0.f);
    for (int c = 0; c < CC; c++) {
        const float* Srow = g_S + (size_t)((b*CC + c)*NN + n) * NN;
        float4 v = ((const float4*)Srow)[tid];
        float lm = fmaxf(fmaxf(v.x, v.y), fmaxf(v.z, v.w));
        #pragma unroll
        for (int off = 16; off; off >>= 1)
            lm = fmaxf(lm, __shfl_xor_sync(0xffffffffu, lm, off));
        if (lane == 0) red[wid] = lm;
        __syncthreads();
        if (tid < 32) {
            float t = (tid < 8) ? red[tid] : -3.4e38f;
            #pragma unroll
            for (int off = 4; off; off >>= 1)
                t = fmaxf(t, __shfl_xor_sync(0xffffffffu, t, off));
            if (tid == 0) red[0] = t;
        }
        __syncthreads();
        float mx = red[0];
        __syncthreads();
        float4 e;
        e.x = __expf(v.x - mx); e.y = __expf(v.y - mx);
        e.z = __expf(v.z - mx); e.w = __expf(v.w - mx);
        float ls = e.x + e.y + e.z + e.w;
        #pragma unroll
        for (int off = 16; off; off >>= 1)
            ls += __shfl_xor_sync(0xffffffffu, ls, off);
        if (lane == 0) red[wid] = ls;
        __syncthreads();
        if (tid < 32) {
            float t = (tid < 8) ? red[tid] : 0.f;
            #pragma unroll
            for (int off = 4; off; off >>= 1)
                t += __shfl_xor_sync(0xffffffffu, t, off);
            if (tid == 0) red[0] = t;
        }
        __syncthreads();
        float Z = red[0];
        float invZ = 1.0f / Z;
        if (tid == 0) {
            g_rowmax[(b*CC + c)*NN + n] = mx;
            g_invZ[(b*CC + c)*NN + n]   = invZ;
        }
        srw.x += e.x * invZ; srw.y += e.y * invZ;
        srw.z += e.z * invZ; srw.w += e.w * invZ;
        __syncthreads();
    }
    ((float4*)&g_sum_edge[(size_t)bn * NN])[tid] = srw;
}

// ---------------- K4: top-16 (+diag) per (b,n) via iterative argmax --------
__global__ void k4_topk(void) {
    __shared__ float buf[NN];
    __shared__ float rv[8];
    __shared__ int   ri[8];
    __shared__ int   sel[MAXI];
    const int bn = blockIdx.x;
    const int n = bn & 1023;
    const int tid = threadIdx.x;
    const int lane = tid & 31, wid = tid >> 5;
    ((float4*)buf)[tid] = ((const float4*)&g_sum_edge[(size_t)bn * NN])[tid];
    __syncthreads();
    for (int it = 0; it < 16; it++) {
        int base = tid * 4;
        float bv = buf[base]; int bi = base;
        #pragma unroll
        for (int q = 1; q < 4; q++) {
            float v = buf[base + q];
            if (v > bv) { bv = v; bi = base + q; }
        }
        #pragma unroll
        for (int off = 16; off; off >>= 1) {
            float ov = __shfl_xor_sync(0xffffffffu, bv, off);
            int   oi = __shfl_xor_sync(0xffffffffu, bi, off);
            if (ov > bv || (ov == bv && oi < bi)) { bv = ov; bi = oi; }
        }
        if (lane == 0) { rv[wid] = bv; ri[wid] = bi; }
        __syncthreads();
        if (tid == 0) {
            float fv = rv[0]; int fi = ri[0];
            for (int w = 1; w < 8; w++)
                if (rv[w] > fv || (rv[w] == fv && ri[w] < fi)) { fv = rv[w]; fi = ri[w]; }
            sel[it] = fi;
            buf[fi] = -3.4e38f;
        }
        __syncthreads();
    }
    if (tid == 0) {
        int cnt = 16;
        bool has = false;
        for (int j = 0; j < 16; j++) if (sel[j] == n) has = true;
        if (!has) { sel[16] = n; cnt = 17; }
        g_cnt[bn] = cnt;
        for (int j = 0; j < cnt; j++) g_idx[bn*MAXI + j] = sel[j];
    }
}

// ---------------- K5: gather attn at mask, row-normalize, colsums, CSC -----
__global__ void k5_gather(void) {
    int gid = blockIdx.x * blockDim.x + threadIdx.x;
    if (gid >= BCN) return;
    int bc = gid >> 10, n = gid & 1023;
    int b = bc >> 3, c = bc & 7;
    int bn = b*NN + n;
    int cnt = g_cnt[bn];
    float mx = g_rowmax[gid], iZ = g_invZ[gid];
    const float* Srow = g_S + (size_t)gid * NN;
    float a[MAXI]; int id[MAXI];
    float rs = 0.f;
    #pragma unroll
    for (int j = 0; j < MAXI; j++) {
        a[j] = 0.f; id[j] = 0;
        if (j < cnt) {
            int m = g_idx[bn*MAXI + j];
            id[j] = m;
            float e = __expf(Srow[m] - mx) * iZ;
            a[j] = e; rs += e;
        }
    }
    float inv = 1.0f / (rs + 1e-6f);
    #pragma unroll
    for (int j = 0; j < MAXI; j++) {
        if (j < cnt) {
            float nr = a[j] * inv;
            g_nr[gid*MAXI + j] = nr;
            atomicAdd(&g_colsum[bc*NN + id[j]], nr);
            if (c == 0) {
                int p = atomicAdd(&g_colcnt[b*NN + id[j]], 1);
                g_colent[(b*NN + id[j])*NN + p] = (n << 5) | j;
            }
        }
    }
}

// ---------------- K5b: invert column sums ----------------------------------
__global__ void k5b_invcol(void) {
    int gid = blockIdx.x * blockDim.x + threadIdx.x;
    if (gid < BCN) g_invcol[gid] = 1.0f / (g_colsum[gid] + 1e-6f);
}

// ---------------- K6: out = norm_row @ norm_col^T (sparse x sparse) --------
__global__ void k6_final(float* __restrict__ out) {
    __shared__ float row[NN];
    const int bcn = blockIdx.x;
    const int bc = bcn >> 10, n = bcn & 1023;
    const int b = bc >> 3;
    const int tid = threadIdx.x;    // 128
    #pragma unroll
    for (int i = 0; i < 2; i++)
        ((float4*)row)[tid + i*128] = make_float4(0.f, 0.f, 0.f, 0.f);
    __syncthreads();
    const int bn = b*NN + n;
    const int cnt = g_cnt[bn];
    for (int j = 0; j < cnt; j++) {
        int k = g_idx[bn*MAXI + j];
        float ai = g_nr[(size_t)bcn*MAXI + j] * g_invcol[bc*NN + k];
        int cc = g_colcnt[b*NN + k];
        const int* ent = &g_colent[(b*NN + k)*NN];
        for (int e = tid; e < cc; e += 128) {
            int pk = ent[e];
            int m = pk >> 5, j2 = pk & 31;
            float ncv = g_nr[(bc*NN + m)*MAXI + j2];
            atomicAdd(&row[m], ai * ncv);
        }
    }
    __syncthreads();
    float* orow = out + (size_t)bcn * NN;
    #pragma unroll
    for (int i = 0; i < 2; i++)
        ((float4*)orow)[tid + i*128] = ((float4*)row)[tid + i*128];
}

// ---------------- launch ----------------------------------------------------
extern "C" void kernel_launch(void* const* d_in, const int* in_sizes, int n_in,
                              void* d_out, int out_size) {
    const float* x = (const float*)d_in[0];     // [4,1024,256]
    const float* W = (const float*)d_in[1];     // [256,4096]
    float* out = (float*)d_out;                 // [4,8,1024,1024]

    k0_splitx<<<(BN * DD) / 256, 256>>>(x);
    k0_splitW<<<dim3(128, 8), dim3(32, 8)>>>(W);
    k1_mma<<<dim3(32, 32), 256>>>();
    k2_mma<<<dim3(8, 8, 32), 256>>>();
    k3_stats<<<BN, 256>>>();
    k4_topk<<<BN, 256>>>();
    k5_gather<<<BCN / 256, 256>>>();
    k5b_invcol<<<BCN / 256, 256>>>();
    k6_final<<<BCN, 128>>>(out);
}

// round 16
// speedup vs baseline: 1.2579x; 1.1850x over previous
#include <cuda_runtime.h>
#include <cuda_bf16.h>
#include <cstdint>

// Problem constants
#define BB 4
#define CC 8
#define NN 1024
#define DD 256
#define BN (BB*NN)          // 4096
#define BCN (BB*CC*NN)      // 32768
#define MAXI 17
#define SCALEF 0.0625f      // D^-0.5 = 1/16

// ---------------- scratch (static device arrays; no allocs) ----------------
__device__ __align__(256) __nv_bfloat16 gx_h[BN*DD], gx_m[BN*DD], gx_l[BN*DD];    // x splits [4096][256]
__device__ __align__(256) __nv_bfloat16 gW_h[BN*DD], gW_m[BN*DD], gW_l[BN*DD];    // W^T splits [4096][256]
__device__ __align__(256) __nv_bfloat16 gq_h[BCN*DD], gq_m[BCN*DD], gq_l[BCN*DD]; // q splits
__device__ __align__(256) __nv_bfloat16 gk_h[BCN*DD], gk_m[BCN*DD], gk_l[BCN*DD]; // k splits

__device__ float g_S[33554432];             // 128 MB scaled logits
__device__ float g_rowmax[BCN];
__device__ float g_invZ[BCN];
__device__ float g_sum_edge[BN*NN];
__device__ int   g_idx[BN*MAXI];
__device__ int   g_cnt[BN];
__device__ float g_nr[BCN*MAXI];
__device__ float g_colsum[BCN];
__device__ float g_invcol[BCN];
__device__ int   g_colcnt[BN];
__device__ int   g_colent[BN*NN];

// ---------------- mma.sync / cp.async helpers (sm_80+ baseline) -------------
#define LDSM4(r0,r1,r2,r3,addr) \
    asm volatile("ldmatrix.sync.aligned.m8n8.x4.shared.b16 {%0,%1,%2,%3}, [%4];" \
                 : "=r"(r0), "=r"(r1), "=r"(r2), "=r"(r3) : "r"(addr))

#define MMA16816(d, a, b0, b1) \
    asm volatile("mma.sync.aligned.m16n8k16.row.col.f32.bf16.bf16.f32 " \
                 "{%0,%1,%2,%3}, {%4,%5,%6,%7}, {%8,%9}, {%0,%1,%2,%3};" \
                 : "+f"((d)[0]), "+f"((d)[1]), "+f"((d)[2]), "+f"((d)[3]) \
                 : "r"((a)[0]), "r"((a)[1]), "r"((a)[2]), "r"((a)[3]), "r"(b0), "r"(b1))

#define CP_COMMIT() asm volatile("cp.async.commit_group;" ::: "memory")
#define CP_WAIT(n)  asm volatile("cp.async.wait_group %0;" :: "n"(n) : "memory")

__device__ __forceinline__ uint32_t smem_u32(const void* p) {
    uint32_t a;
    asm("{ .reg .u64 t; cvta.to.shared.u64 t, %1; cvt.u32.u64 %0, t; }" : "=r"(a) : "l"(p));
    return a;
}

// Async-prefetch one [128 rows x 64 bf16] SW128-swizzled tile (16 KB)
__device__ __forceinline__ void cp_tile(uint32_t dst, const __nv_bfloat16* src,
                                        int row0, int kc, int tid) {
    const char* s = (const char*)src + (size_t)row0 * 512 + kc * 128;
    #pragma unroll
    for (int i = 0; i < 4; i++) {
        int idx = tid + i * 256;           // 0..1023 (128 rows x 8 segs)
        int r = idx >> 3, seg = idx & 7;
        int off = r * 128 + seg * 16;
        uint32_t d = dst + (off ^ ((off >> 3) & 0x70));
        const void* g = s + (size_t)r * 512 + seg * 16;
        asm volatile("cp.async.cg.shared.global [%0], [%1], 16;" :: "r"(d), "l"(g) : "memory");
    }
}

__device__ __forceinline__ void split3(float v, __nv_bfloat16& h, __nv_bfloat16& m, __nv_bfloat16& l) {
    h = __float2bfloat16(v);
    float r1 = v - __bfloat162float(h);
    m = __float2bfloat16(r1);
    float r2 = r1 - __bfloat162float(m);
    l = __float2bfloat16(r2);
}

// ---------------- K0a: split x into bf16 hi/mid/lo --------------------------
__global__ void k0_splitx(const float* __restrict__ x) {
    int i = blockIdx.x * 256 + threadIdx.x;
    float v = x[i];
    __nv_bfloat16 h, m, l;
    split3(v, h, m, l);
    gx_h[i] = h; gx_m[i] = m; gx_l[i] = l;
}

// ---------------- K0b: transpose W [256][4096] -> W^T splits [4096][256] ----
__global__ void k0_splitW(const float* __restrict__ W) {
    __shared__ float t[32][33];
    int j0 = blockIdx.x * 32, k0 = blockIdx.y * 32;
    int tx = threadIdx.x, ty = threadIdx.y;     // (32,8)
    #pragma unroll
    for (int i = 0; i < 4; i++)
        t[ty + i * 8][tx] = W[(size_t)(k0 + ty + i * 8) * 4096 + j0 + tx];
    __syncthreads();
    #pragma unroll
    for (int i = 0; i < 4; i++) {
        int j = j0 + ty + i * 8;
        float v = t[tx][ty + i * 8];
        __nv_bfloat16 h, m, l;
        split3(v, h, m, l);
        size_t o = (size_t)j * 256 + k0 + tx;
        gW_h[o] = h; gW_m[o] = m; gW_l[o] = l;
    }
}

// ======================= shared mainloop ====================================
// 8 warps; warp tile 64(m) x 32(n); block tile 128x128; K-chunk 64.
// 6 split-term passes x 4 k-chunks = 24 tile iterations, double-buffered.
__device__ __forceinline__ void mma_chunk(uint32_t sA, uint32_t sB,
                                          int wm, int wn, int lane,
                                          float acc[4][4][4]) {
    #pragma unroll
    for (int kk = 0; kk < 4; kk++) {
        const int kb = kk * 32 + (lane >> 4) * 16;  // byte offset in 128B row
        uint32_t a[4][4];
        #pragma unroll
        for (int mi = 0; mi < 4; mi++) {
            int row = wm + mi * 16 + (lane & 15);
            int off = row * 128 + kb;
            LDSM4(a[mi][0], a[mi][1], a[mi][2], a[mi][3],
                  sA + (off ^ ((off >> 3) & 0x70)));
        }
        uint32_t b[2][4];
        #pragma unroll
        for (int nj = 0; nj < 2; nj++) {
            int row = wn + nj * 16 + (lane & 15);
            int off = row * 128 + kb;
            LDSM4(b[nj][0], b[nj][1], b[nj][2], b[nj][3],
                  sB + (off ^ ((off >> 3) & 0x70)));
        }
        #pragma unroll
        for (int mi = 0; mi < 4; mi++)
            #pragma unroll
            for (int ni = 0; ni < 4; ni++)
                MMA16816(acc[mi][ni], a[mi], b[ni >> 1][ni & 1], b[ni >> 1][(ni & 1) + 2]);
    }
}

// Pipelined 24-chunk mainloop over 6 term pairs (rowA0/rowB0 are global row bases)
__device__ __forceinline__ void gemm_mainloop(
        const __nv_bfloat16* const* As, const __nv_bfloat16* const* Bs,
        int rowA0, int rowB0, int tid, int wm, int wn, int lane,
        float acc[4][4][4]) {
    extern __shared__ __align__(128) char dyn[];
    // layout: A0 A1 B0 B1, each 16 KB
    uint32_t base = smem_u32(dyn);
    uint32_t bufA[2] = { base,          base + 16384 };
    uint32_t bufB[2] = { base + 32768,  base + 49152 };

    cp_tile(bufA[0], As[0], rowA0, 0, tid);
    cp_tile(bufB[0], Bs[0], rowB0, 0, tid);
    CP_COMMIT();

    for (int ch = 0; ch < 24; ch++) {
        int nx = ch + 1;
        if (nx < 24) {
            cp_tile(bufA[nx & 1], As[nx >> 2], rowA0, nx & 3, tid);
            cp_tile(bufB[nx & 1], Bs[nx >> 2], rowB0, nx & 3, tid);
            CP_COMMIT();
            CP_WAIT(1);
        } else {
            CP_WAIT(0);
        }
        __syncthreads();
        mma_chunk(bufA[ch & 1], bufB[ch & 1], wm, wn, lane, acc);
        __syncthreads();
    }
}

// ---------------- K1: y = x @ W (6-term bf16 split), split epilogue --------
__global__ void __launch_bounds__(256, 2) k1_mma() {
    const int tid = threadIdx.x, wid = tid >> 5, lane = tid & 31;
    const int wm = (wid & 1) * 64, wn = (wid >> 1) * 32;

    const int m0 = blockIdx.y * 128;   // token rows
    const int n0 = blockIdx.x * 128;   // output cols

    float acc[4][4][4];
    #pragma unroll
    for (int mi = 0; mi < 4; mi++)
        #pragma unroll
        for (int ni = 0; ni < 4; ni++)
            #pragma unroll
            for (int e = 0; e < 4; e++) acc[mi][ni][e] = 0.f;

    const __nv_bfloat16* As[6] = {gx_h, gx_h, gx_m, gx_h, gx_m, gx_l};
    const __nv_bfloat16* Bs[6] = {gW_h, gW_m, gW_h, gW_l, gW_m, gW_h};
    gemm_mainloop(As, Bs, m0, n0, tid, wm, wn, lane, acc);

    // epilogue: split y -> q/k bf16 hi/mid/lo (in-place residual on acc)
    const int s = n0 >> 11, c = (n0 >> 8) & 7, d0 = (n0 & 255) + wn;
    __nv_bfloat16* const dsts[3] = { s ? gk_h : gq_h, s ? gk_m : gq_m, s ? gk_l : gq_l };
    #pragma unroll
    for (int sp = 0; sp < 3; sp++) {
        __nv_bfloat16* dst = dsts[sp];
        #pragma unroll
        for (int mi = 0; mi < 4; mi++) {
            #pragma unroll
            for (int half = 0; half < 2; half++) {
                int row = m0 + wm + mi * 16 + (lane >> 2) + half * 8;   // token
                int b = row >> 10, n = row & 1023;
                size_t base = ((size_t)(b * CC + c) * NN + n) * DD + d0;
                #pragma unroll
                for (int ni = 0; ni < 4; ni++) {
                    float v0 = acc[mi][ni][half * 2 + 0];
                    float v1 = acc[mi][ni][half * 2 + 1];
                    __nv_bfloat16 h0 = __float2bfloat16(v0);
                    __nv_bfloat16 h1 = __float2bfloat16(v1);
                    __nv_bfloat162 p; p.x = h0; p.y = h1;
                    *(__nv_bfloat162*)&dst[base + ni * 8 + (lane & 3) * 2] = p;
                    acc[mi][ni][half * 2 + 0] = v0 - __bfloat162float(h0);
                    acc[mi][ni][half * 2 + 1] = v1 - __bfloat162float(h1);
                }
            }
        }
    }
}

// ---------------- K2: S = scale * q @ k^T (6-term bf16 split) ---------------
__global__ void __launch_bounds__(256, 2) k2_mma() {
    const int tid = threadIdx.x, wid = tid >> 5, lane = tid & 31;
    const int wm = (wid & 1) * 64, wn = (wid >> 1) * 32;

    const int bc = blockIdx.z;
    const int rowA0 = bc * NN + blockIdx.y * 128;   // q rows -> S rows
    const int rowB0 = bc * NN + blockIdx.x * 128;   // k rows -> S cols
    const int m0 = blockIdx.x * 128;

    float acc[4][4][4];
    #pragma unroll
    for (int mi = 0; mi < 4; mi++)
        #pragma unroll
        for (int ni = 0; ni < 4; ni++)
            #pragma unroll
            for (int e = 0; e < 4; e++) acc[mi][ni][e] = 0.f;

    const __nv_bfloat16* As[6] = {gq_h, gq_h, gq_m, gq_h, gq_m, gq_l};
    const __nv_bfloat16* Bs[6] = {gk_h, gk_m, gk_h, gk_l, gk_m, gk_h};
    gemm_mainloop(As, Bs, rowA0, rowB0, tid, wm, wn, lane, acc);

    // epilogue: scale & store fp32 logits (coalesced float2)
    #pragma unroll
    for (int mi = 0; mi < 4; mi++) {
        #pragma unroll
        for (int half = 0; half < 2; half++) {
            int srow = blockIdx.y * 128 + wm + mi * 16 + (lane >> 2) + half * 8;
            float* Sr = g_S + ((size_t)bc * NN + srow) * NN + m0 + wn;
            #pragma unroll
            for (int ni = 0; ni < 4; ni++) {
                float2 v;
                v.x = acc[mi][ni][half * 2 + 0] * SCALEF;
                v.y = acc[mi][ni][half * 2 + 1] * SCALEF;
                *(float2*)&Sr[ni * 8 + (lane & 3) * 2] = v;
            }
        }
    }
}

// ---------------- K3: per-row softmax stats + channel-summed sum_edge ------
__global__ void k3_stats(void) {
    __shared__ float red[32];
    const int bn = blockIdx.x;
    const int b = bn >> 10, n = bn & 1023;
    const int tid = threadIdx.x;
    const int lane = tid & 31, wid = tid >> 5;

    if (tid == 0) g_colcnt[bn] = 0;
    if (tid < CC) g_colsum[(b*CC + tid)*NN + n] = 0.f;

    float4 srw = make_float4(0.f, 0.f, 0.f, 0.f);
    for (int c = 0; c < CC; c++) {
        const float* Srow = g_S + (size_t)((b*CC + c)*NN + n) * NN;
        float4 v = ((const float4*)Srow)[tid];
        float lm = fmaxf(fmaxf(v.x, v.y), fmaxf(v.z, v.w));
        #pragma unroll
        for (int off = 16; off; off >>= 1)
            lm = fmaxf(lm, __shfl_xor_sync(0xffffffffu, lm, off));
        if (lane == 0) red[wid] = lm;
        __syncthreads();
        if (tid < 32) {
            float t = (tid < 8) ? red[tid] : -3.4e38f;
            #pragma unroll
            for (int off = 4; off; off >>= 1)
                t = fmaxf(t, __shfl_xor_sync(0xffffffffu, t, off));
            if (tid == 0) red[0] = t;
        }
        __syncthreads();
        float mx = red[0];
        __syncthreads();
        float4 e;
        e.x = __expf(v.x - mx); e.y = __expf(v.y - mx);
        e.z = __expf(v.z - mx); e.w = __expf(v.w - mx);
        float ls = e.x + e.y + e.z + e.w;
        #pragma unroll
        for (int off = 16; off; off >>= 1)
            ls += __shfl_xor_sync(0xffffffffu, ls, off);
        if (lane == 0) red[wid] = ls;
        __syncthreads();
        if (tid < 32) {
            float t = (tid < 8) ? red[tid] : 0.f;
            #pragma unroll
            for (int off = 4; off; off >>= 1)
                t += __shfl_xor_sync(0xffffffffu, t, off);
            if (tid == 0) red[0] = t;
        }
        __syncthreads();
        float Z = red[0];
        float invZ = 1.0f / Z;
        if (tid == 0) {
            g_rowmax[(b*CC + c)*NN + n] = mx;
            g_invZ[(b*CC + c)*NN + n]   = invZ;
        }
        srw.x += e.x * invZ; srw.y += e.y * invZ;
        srw.z += e.z * invZ; srw.w += e.w * invZ;
        __syncthreads();
    }
    ((float4*)&g_sum_edge[(size_t)bn * NN])[tid] = srw;
}

// ---------------- K4: top-16 (+diag) per (b,n) via iterative argmax --------
__global__ void k4_topk(void) {
    __shared__ float buf[NN];
    __shared__ float rv[8];
    __shared__ int   ri[8];
    __shared__ int   sel[MAXI];
    const int bn = blockIdx.x;
    const int n = bn & 1023;
    const int tid = threadIdx.x;
    const int lane = tid & 31, wid = tid >> 5;
    ((float4*)buf)[tid] = ((const float4*)&g_sum_edge[(size_t)bn * NN])[tid];
    __syncthreads();
    for (int it = 0; it < 16; it++) {
        int base = tid * 4;
        float bv = buf[base]; int bi = base;
        #pragma unroll
        for (int q = 1; q < 4; q++) {
            float v = buf[base + q];
            if (v > bv) { bv = v; bi = base + q; }
        }
        #pragma unroll
        for (int off = 16; off; off >>= 1) {
            float ov = __shfl_xor_sync(0xffffffffu, bv, off);
            int   oi = __shfl_xor_sync(0xffffffffu, bi, off);
            if (ov > bv || (ov == bv && oi < bi)) { bv = ov; bi = oi; }
        }
        if (lane == 0) { rv[wid] = bv; ri[wid] = bi; }
        __syncthreads();
        if (tid == 0) {
            float fv = rv[0]; int fi = ri[0];
            for (int w = 1; w < 8; w++)
                if (rv[w] > fv || (rv[w] == fv && ri[w] < fi)) { fv = rv[w]; fi = ri[w]; }
            sel[it] = fi;
            buf[fi] = -3.4e38f;
        }
        __syncthreads();
    }
    if (tid == 0) {
        int cnt = 16;
        bool has = false;
        for (int j = 0; j < 16; j++) if (sel[j] == n) has = true;
        if (!has) { sel[16] = n; cnt = 17; }
        g_cnt[bn] = cnt;
        for (int j = 0; j < cnt; j++) g_idx[bn*MAXI + j] = sel[j];
    }
}

// ---------------- K5: gather attn at mask, row-normalize, colsums, CSC -----
__global__ void k5_gather(void) {
    int gid = blockIdx.x * blockDim.x + threadIdx.x;
    if (gid >= BCN) return;
    int bc = gid >> 10, n = gid & 1023;
    int b = bc >> 3, c = bc & 7;
    int bn = b*NN + n;
    int cnt = g_cnt[bn];
    float mx = g_rowmax[gid], iZ = g_invZ[gid];
    const float* Srow = g_S + (size_t)gid * NN;
    float a[MAXI]; int id[MAXI];
    float rs = 0.f;
    #pragma unroll
    for (int j = 0; j < MAXI; j++) {
        a[j] = 0.f; id[j] = 0;
        if (j < cnt) {
            int m = g_idx[bn*MAXI + j];
            id[j] = m;
            float e = __expf(Srow[m] - mx) * iZ;
            a[j] = e; rs += e;
        }
    }
    float inv = 1.0f / (rs + 1e-6f);
    #pragma unroll
    for (int j = 0; j < MAXI; j++) {
        if (j < cnt) {
            float nr = a[j] * inv;
            g_nr[gid*MAXI + j] = nr;
            atomicAdd(&g_colsum[bc*NN + id[j]], nr);
            if (c == 0) {
                int p = atomicAdd(&g_colcnt[b*NN + id[j]], 1);
                g_colent[(b*NN + id[j])*NN + p] = (n << 5) | j;
            }
        }
    }
}

// ---------------- K5b: invert column sums ----------------------------------
__global__ void k5b_invcol(void) {
    int gid = blockIdx.x * blockDim.x + threadIdx.x;
    if (gid < BCN) g_invcol[gid] = 1.0f / (g_colsum[gid] + 1e-6f);
}

// ---------------- K6: out = norm_row @ norm_col^T (sparse x sparse) --------
__global__ void k6_final(float* __restrict__ out) {
    __shared__ float row[NN];
    const int bcn = blockIdx.x;
    const int bc = bcn >> 10, n = bcn & 1023;
    const int b = bc >> 3;
    const int tid = threadIdx.x;    // 128
    #pragma unroll
    for (int i = 0; i < 2; i++)
        ((float4*)row)[tid + i*128] = make_float4(0.f, 0.f, 0.f, 0.f);
    __syncthreads();
    const int bn = b*NN + n;
    const int cnt = g_cnt[bn];
    for (int j = 0; j < cnt; j++) {
        int k = g_idx[bn*MAXI + j];
        float ai = g_nr[(size_t)bcn*MAXI + j] * g_invcol[bc*NN + k];
        int cc = g_colcnt[b*NN + k];
        const int* ent = &g_colent[(b*NN + k)*NN];
        for (int e = tid; e < cc; e += 128) {
            int pk = ent[e];
            int m = pk >> 5, j2 = pk & 31;
            float ncv = g_nr[(bc*NN + m)*MAXI + j2];
            atomicAdd(&row[m], ai * ncv);
        }
    }
    __syncthreads();
    float* orow = out + (size_t)bcn * NN;
    #pragma unroll
    for (int i = 0; i < 2; i++)
        ((float4*)orow)[tid + i*128] = ((float4*)row)[tid + i*128];
}

// ---------------- launch ----------------------------------------------------
extern "C" void kernel_launch(void* const* d_in, const int* in_sizes, int n_in,
                              void* d_out, int out_size) {
    const float* x = (const float*)d_in[0];     // [4,1024,256]
    const float* W = (const float*)d_in[1];     // [256,4096]
    float* out = (float*)d_out;                 // [4,8,1024,1024]

    const int DYN = 65536;   // 4 x 16 KB tile buffers
    cudaFuncSetAttribute(k1_mma, cudaFuncAttributeMaxDynamicSharedMemorySize, DYN);
    cudaFuncSetAttribute(k2_mma, cudaFuncAttributeMaxDynamicSharedMemorySize, DYN);

    k0_splitx<<<(BN * DD) / 256, 256>>>(x);
    k0_splitW<<<dim3(128, 8), dim3(32, 8)>>>(W);
    k1_mma<<<dim3(32, 32), 256, DYN>>>();
    k2_mma<<<dim3(8, 8, 32), 256, DYN>>>();
    k3_stats<<<BN, 256>>>();
    k4_topk<<<BN, 256>>>();
    k5_gather<<<BCN / 256, 256>>>();
    k5b_invcol<<<BCN / 256, 256>>>();
    k6_final<<<BCN, 128>>>(out);
}

// round 17
// speedup vs baseline: 1.3460x; 1.0700x over previous
#include <cuda_runtime.h>
#include <cuda_bf16.h>
#include <cstdint>

// Problem constants
#define BB 4
#define CC 8
#define NN 1024
#define DD 256
#define BN (BB*NN)          // 4096
#define BCN (BB*CC*NN)      // 32768
#define MAXI 17
#define SCALEF 0.0625f      // D^-0.5 = 1/16

// ---------------- scratch (static device arrays; no allocs) ----------------
__device__ __align__(256) __nv_bfloat16 gx_h[BN*DD], gx_m[BN*DD], gx_l[BN*DD];    // x splits [4096][256]
__device__ __align__(256) __nv_bfloat16 gW_h[BN*DD], gW_m[BN*DD], gW_l[BN*DD];    // W^T splits [4096][256]
__device__ __align__(256) __nv_bfloat16 gq_h[BCN*DD], gq_m[BCN*DD], gq_l[BCN*DD]; // q splits
__device__ __align__(256) __nv_bfloat16 gk_h[BCN*DD], gk_m[BCN*DD], gk_l[BCN*DD]; // k splits

__device__ float g_S[33554432];             // 128 MB scaled logits
__device__ float g_rowmax[BCN];
__device__ float g_invZ[BCN];
__device__ float g_sum_edge[BN*NN];
__device__ int   g_idx[BN*MAXI];
__device__ int   g_cnt[BN];
__device__ float g_nr[BCN*MAXI];
__device__ float g_colsum[BCN];
__device__ float g_invcol[BCN];
__device__ int   g_colcnt[BN];
__device__ int   g_colent[BN*NN];

// ---------------- mma.sync / cp.async helpers (sm_80+ baseline) -------------
#define LDSM4(r0,r1,r2,r3,addr) \
    asm volatile("ldmatrix.sync.aligned.m8n8.x4.shared.b16 {%0,%1,%2,%3}, [%4];" \
                 : "=r"(r0), "=r"(r1), "=r"(r2), "=r"(r3) : "r"(addr))

#define MMA16816(d, a, b0, b1) \
    asm volatile("mma.sync.aligned.m16n8k16.row.col.f32.bf16.bf16.f32 " \
                 "{%0,%1,%2,%3}, {%4,%5,%6,%7}, {%8,%9}, {%0,%1,%2,%3};" \
                 : "+f"((d)[0]), "+f"((d)[1]), "+f"((d)[2]), "+f"((d)[3]) \
                 : "r"((a)[0]), "r"((a)[1]), "r"((a)[2]), "r"((a)[3]), "r"(b0), "r"(b1))

#define CP_COMMIT() asm volatile("cp.async.commit_group;" ::: "memory")
#define CP_WAIT(n)  asm volatile("cp.async.wait_group %0;" :: "n"(n) : "memory")

__device__ __forceinline__ uint32_t smem_u32(const void* p) {
    uint32_t a;
    asm("{ .reg .u64 t; cvta.to.shared.u64 t, %1; cvt.u32.u64 %0, t; }" : "=r"(a) : "l"(p));
    return a;
}

// Async-prefetch one [128 rows x 64 bf16] SW128-swizzled tile (16 KB)
__device__ __forceinline__ void cp_tile(uint32_t dst, const __nv_bfloat16* src,
                                        int row0, int kc, int tid) {
    const char* s = (const char*)src + (size_t)row0 * 512 + kc * 128;
    #pragma unroll
    for (int i = 0; i < 4; i++) {
        int idx = tid + i * 256;           // 0..1023 (128 rows x 8 segs)
        int r = idx >> 3, seg = idx & 7;
        int off = r * 128 + seg * 16;
        uint32_t d = dst + (off ^ ((off >> 3) & 0x70));
        const void* g = s + (size_t)r * 512 + seg * 16;
        asm volatile("cp.async.cg.shared.global [%0], [%1], 16;" :: "r"(d), "l"(g) : "memory");
    }
}

__device__ __forceinline__ void split3(float v, __nv_bfloat16& h, __nv_bfloat16& m, __nv_bfloat16& l) {
    h = __float2bfloat16(v);
    float r1 = v - __bfloat162float(h);
    m = __float2bfloat16(r1);
    float r2 = r1 - __bfloat162float(m);
    l = __float2bfloat16(r2);
}

// ---------------- K0a: split x into bf16 hi/mid/lo --------------------------
__global__ void k0_splitx(const float* __restrict__ x) {
    int i = blockIdx.x * 256 + threadIdx.x;
    float v = x[i];
    __nv_bfloat16 h, m, l;
    split3(v, h, m, l);
    gx_h[i] = h; gx_m[i] = m; gx_l[i] = l;
}

// ---------------- K0b: transpose W [256][4096] -> W^T splits [4096][256] ----
__global__ void k0_splitW(const float* __restrict__ W) {
    __shared__ float t[32][33];
    int j0 = blockIdx.x * 32, k0 = blockIdx.y * 32;
    int tx = threadIdx.x, ty = threadIdx.y;     // (32,8)
    #pragma unroll
    for (int i = 0; i < 4; i++)
        t[ty + i * 8][tx] = W[(size_t)(k0 + ty + i * 8) * 4096 + j0 + tx];
    __syncthreads();
    #pragma unroll
    for (int i = 0; i < 4; i++) {
        int j = j0 + ty + i * 8;
        float v = t[tx][ty + i * 8];
        __nv_bfloat16 h, m, l;
        split3(v, h, m, l);
        size_t o = (size_t)j * 256 + k0 + tx;
        gW_h[o] = h; gW_m[o] = m; gW_l[o] = l;
    }
}

// ======================= shared mainloop ====================================
// 8 warps; warp tile 64(m) x 32(n); block tile 128x128; K-chunk 64.
// 6 split-term passes x 4 k-chunks = 24 chunks; 3-stage cp.async pipeline,
// ONE barrier per chunk (cp issue after mma; stage being overwritten was
// consumed one chunk ago, protected by the loop-top barrier).
// Swizzle XOR for this layout = (lane&7)<<4, thread-constant (rows == 0 mod 8).
__device__ __forceinline__ void mma_chunk(uint32_t sA, uint32_t sB,
                                          int wm, int wn, int lane,
                                          float acc[4][4][4]) {
    const int rlow = lane & 15;
    const uint32_t xorv = (uint32_t)(lane & 7) << 4;
    const uint32_t kbase = (uint32_t)(lane >> 4) * 16;
    uint32_t aoff[4], boff[2];
    #pragma unroll
    for (int mi = 0; mi < 4; mi++) aoff[mi] = sA + (wm + mi * 16 + rlow) * 128;
    #pragma unroll
    for (int nj = 0; nj < 2; nj++) boff[nj] = sB + (wn + nj * 16 + rlow) * 128;

    #pragma unroll
    for (int kk = 0; kk < 4; kk++) {
        const uint32_t kbx = ((uint32_t)(kk * 32) + kbase) ^ xorv;
        uint32_t a[4][4];
        #pragma unroll
        for (int mi = 0; mi < 4; mi++)
            LDSM4(a[mi][0], a[mi][1], a[mi][2], a[mi][3], aoff[mi] + kbx);
        uint32_t b[2][4];
        #pragma unroll
        for (int nj = 0; nj < 2; nj++)
            LDSM4(b[nj][0], b[nj][1], b[nj][2], b[nj][3], boff[nj] + kbx);
        #pragma unroll
        for (int mi = 0; mi < 4; mi++)
            #pragma unroll
            for (int ni = 0; ni < 4; ni++)
                MMA16816(acc[mi][ni], a[mi], b[ni >> 1][ni & 1], b[ni >> 1][(ni & 1) + 2]);
    }
}

__device__ __forceinline__ void gemm_mainloop(
        const __nv_bfloat16* const* As, const __nv_bfloat16* const* Bs,
        int rowA0, int rowB0, int tid, int wm, int wn, int lane,
        float acc[4][4][4]) {
    extern __shared__ __align__(128) char dyn[];
    uint32_t base = smem_u32(dyn);
    // stage s at base + s*32768: [A 16KB][B 16KB]
    uint32_t stA[3] = { base, base + 32768, base + 65536 };
    uint32_t stB[3] = { base + 16384, base + 49152, base + 81920 };

    cp_tile(stA[0], As[0], rowA0, 0, tid);
    cp_tile(stB[0], Bs[0], rowB0, 0, tid);
    CP_COMMIT();
    cp_tile(stA[1], As[0], rowA0, 1, tid);
    cp_tile(stB[1], Bs[0], rowB0, 1, tid);
    CP_COMMIT();

    #pragma unroll 1
    for (int ch = 0; ch < 24; ch++) {
        if (ch < 23) { CP_WAIT(1); } else { CP_WAIT(0); }
        __syncthreads();
        const int st = ch % 3;
        mma_chunk(stA[st], stB[st], wm, wn, lane, acc);
        const int nx = ch + 2;
        if (nx < 24) {
            const int sn = nx % 3;
            cp_tile(stA[sn], As[nx >> 2], rowA0, nx & 3, tid);
            cp_tile(stB[sn], Bs[nx >> 2], rowB0, nx & 3, tid);
            CP_COMMIT();
        }
    }
}

// ---------------- K1: y = x @ W (6-term bf16 split), split epilogue --------
__global__ void __launch_bounds__(256, 2) k1_mma() {
    const int tid = threadIdx.x, wid = tid >> 5, lane = tid & 31;
    const int wm = (wid & 1) * 64, wn = (wid >> 1) * 32;

    const int m0 = blockIdx.y * 128;   // token rows
    const int n0 = blockIdx.x * 128;   // output cols

    float acc[4][4][4];
    #pragma unroll
    for (int mi = 0; mi < 4; mi++)
        #pragma unroll
        for (int ni = 0; ni < 4; ni++)
            #pragma unroll
            for (int e = 0; e < 4; e++) acc[mi][ni][e] = 0.f;

    const __nv_bfloat16* As[6] = {gx_h, gx_h, gx_m, gx_h, gx_m, gx_l};
    const __nv_bfloat16* Bs[6] = {gW_h, gW_m, gW_h, gW_l, gW_m, gW_h};
    gemm_mainloop(As, Bs, m0, n0, tid, wm, wn, lane, acc);

    // epilogue: split y -> q/k bf16 hi/mid/lo (in-place residual on acc)
    const int s = n0 >> 11, c = (n0 >> 8) & 7, d0 = (n0 & 255) + wn;
    __nv_bfloat16* const dsts[3] = { s ? gk_h : gq_h, s ? gk_m : gq_m, s ? gk_l : gq_l };
    #pragma unroll
    for (int sp = 0; sp < 3; sp++) {
        __nv_bfloat16* dst = dsts[sp];
        #pragma unroll
        for (int mi = 0; mi < 4; mi++) {
            #pragma unroll
            for (int half = 0; half < 2; half++) {
                int row = m0 + wm + mi * 16 + (lane >> 2) + half * 8;   // token
                int b = row >> 10, n = row & 1023;
                size_t base = ((size_t)(b * CC + c) * NN + n) * DD + d0;
                #pragma unroll
                for (int ni = 0; ni < 4; ni++) {
                    float v0 = acc[mi][ni][half * 2 + 0];
                    float v1 = acc[mi][ni][half * 2 + 1];
                    __nv_bfloat16 h0 = __float2bfloat16(v0);
                    __nv_bfloat16 h1 = __float2bfloat16(v1);
                    __nv_bfloat162 p; p.x = h0; p.y = h1;
                    *(__nv_bfloat162*)&dst[base + ni * 8 + (lane & 3) * 2] = p;
                    acc[mi][ni][half * 2 + 0] = v0 - __bfloat162float(h0);
                    acc[mi][ni][half * 2 + 1] = v1 - __bfloat162float(h1);
                }
            }
        }
    }
}

// ---------------- K2: S = scale * q @ k^T (6-term bf16 split) ---------------
__global__ void __launch_bounds__(256, 2) k2_mma() {
    const int tid = threadIdx.x, wid = tid >> 5, lane = tid & 31;
    const int wm = (wid & 1) * 64, wn = (wid >> 1) * 32;

    const int bc = blockIdx.z;
    const int rowA0 = bc * NN + blockIdx.y * 128;   // q rows -> S rows
    const int rowB0 = bc * NN + blockIdx.x * 128;   // k rows -> S cols
    const int m0 = blockIdx.x * 128;

    float acc[4][4][4];
    #pragma unroll
    for (int mi = 0; mi < 4; mi++)
        #pragma unroll
        for (int ni = 0; ni < 4; ni++)
            #pragma unroll
            for (int e = 0; e < 4; e++) acc[mi][ni][e] = 0.f;

    const __nv_bfloat16* As[6] = {gq_h, gq_h, gq_m, gq_h, gq_m, gq_l};
    const __nv_bfloat16* Bs[6] = {gk_h, gk_m, gk_h, gk_l, gk_m, gk_h};
    gemm_mainloop(As, Bs, rowA0, rowB0, tid, wm, wn, lane, acc);

    // epilogue: scale & store fp32 logits (coalesced float2)
    #pragma unroll
    for (int mi = 0; mi < 4; mi++) {
        #pragma unroll
        for (int half = 0; half < 2; half++) {
            int srow = blockIdx.y * 128 + wm + mi * 16 + (lane >> 2) + half * 8;
            float* Sr = g_S + ((size_t)bc * NN + srow) * NN + m0 + wn;
            #pragma unroll
            for (int ni = 0; ni < 4; ni++) {
                float2 v;
                v.x = acc[mi][ni][half * 2 + 0] * SCALEF;
                v.y = acc[mi][ni][half * 2 + 1] * SCALEF;
                *(float2*)&Sr[ni * 8 + (lane & 3) * 2] = v;
            }
        }
    }
}

// ---------------- K3: warp-per-channel softmax stats + channel sum ----------
// Block = one (b,n); warp w = channel w. Shfl-only reductions, 1 barrier.
__global__ void k3_stats(void) {
    __shared__ float4 contrib[CC][256];
    const int bn = blockIdx.x;
    const int b = bn >> 10, n = bn & 1023;
    const int tid = threadIdx.x;
    const int lane = tid & 31, w = tid >> 5;   // w = channel

    if (tid == 0) g_colcnt[bn] = 0;
    if (tid < CC) g_colsum[(b*CC + tid)*NN + n] = 0.f;

    const float* Srow = g_S + (size_t)((b*CC + w)*NN + n) * NN;
    float4 v[8];
    #pragma unroll
    for (int j = 0; j < 8; j++) v[j] = ((const float4*)Srow)[lane + 32*j];

    float mx = -3.4e38f;
    #pragma unroll
    for (int j = 0; j < 8; j++)
        mx = fmaxf(mx, fmaxf(fmaxf(v[j].x, v[j].y), fmaxf(v[j].z, v[j].w)));
    #pragma unroll
    for (int off = 16; off; off >>= 1)
        mx = fmaxf(mx, __shfl_xor_sync(0xffffffffu, mx, off));

    float ls = 0.f;
    #pragma unroll
    for (int j = 0; j < 8; j++) {
        v[j].x = __expf(v[j].x - mx); v[j].y = __expf(v[j].y - mx);
        v[j].z = __expf(v[j].z - mx); v[j].w = __expf(v[j].w - mx);
        ls += (v[j].x + v[j].y) + (v[j].z + v[j].w);
    }
    #pragma unroll
    for (int off = 16; off; off >>= 1)
        ls += __shfl_xor_sync(0xffffffffu, ls, off);

    float invZ = 1.0f / ls;
    if (lane == 0) {
        g_rowmax[(b*CC + w)*NN + n] = mx;
        g_invZ[(b*CC + w)*NN + n]   = invZ;
    }
    #pragma unroll
    for (int j = 0; j < 8; j++) {
        float4 e = v[j];
        e.x *= invZ; e.y *= invZ; e.z *= invZ; e.w *= invZ;
        contrib[w][lane + 32*j] = e;
    }
    __syncthreads();

    float4 s = contrib[0][tid];
    #pragma unroll
    for (int c = 1; c < CC; c++) {
        float4 t = contrib[c][tid];
        s.x += t.x; s.y += t.y; s.z += t.z; s.w += t.w;
    }
    ((float4*)&g_sum_edge[(size_t)bn * NN])[tid] = s;
}

// ---------------- K4: top-16 (+diag), one WARP per row, no barriers --------
__global__ void k4_topk(void) {
    const int wid = threadIdx.x >> 5, lane = threadIdx.x & 31;
    const int bn = blockIdx.x * 8 + wid;
    const int n = bn & 1023;
    const float* src = &g_sum_edge[(size_t)bn * NN];

    float v[32];
    #pragma unroll
    for (int j = 0; j < 32; j++) v[j] = src[j * 32 + lane];

    // per-lane running (max, argj) with cleared-bitmask (regs stay static-indexed)
    uint32_t cleared = 0;
    float lm = v[0]; int lj = 0;
    #pragma unroll
    for (int j = 1; j < 32; j++)
        if (v[j] > lm) { lm = v[j]; lj = j; }

    int selreg = -1;
    for (int it = 0; it < 16; it++) {
        float bv = lm; int bi = lj * 32 + lane;
        #pragma unroll
        for (int off = 16; off; off >>= 1) {
            float ov = __shfl_xor_sync(0xffffffffu, bv, off);
            int   oi = __shfl_xor_sync(0xffffffffu, bi, off);
            if (ov > bv || (ov == bv && oi < bi)) { bv = ov; bi = oi; }
        }
        if (lane == it) selreg = bi;
        if (bi == lj * 32 + lane) {          // this lane owned the winner
            cleared |= (1u << lj);
            lm = -3.4e38f; lj = 0;
            #pragma unroll
            for (int j = 0; j < 32; j++)
                if (!((cleared >> j) & 1u) && v[j] > lm) { lm = v[j]; lj = j; }
        }
    }
    unsigned ball = __ballot_sync(0xffffffffu, lane < 16 && selreg == n);
    int has = (ball != 0);
    if (lane < 16) g_idx[bn * MAXI + lane] = selreg;
    if (!has && lane == 16) g_idx[bn * MAXI + 16] = n;
    if (lane == 0) g_cnt[bn] = has ? 16 : 17;
}

// ---------------- K5: gather attn at mask, row-normalize, colsums, CSC -----
__global__ void k5_gather(void) {
    int gid = blockIdx.x * blockDim.x + threadIdx.x;
    if (gid >= BCN) return;
    int bc = gid >> 10, n = gid & 1023;
    int b = bc >> 3, c = bc & 7;
    int bn = b*NN + n;
    int cnt = g_cnt[bn];
    float mx = g_rowmax[gid], iZ = g_invZ[gid];
    const float* Srow = g_S + (size_t)gid * NN;
    float a[MAXI]; int id[MAXI];
    float rs = 0.f;
    #pragma unroll
    for (int j = 0; j < MAXI; j++) {
        a[j] = 0.f; id[j] = 0;
        if (j < cnt) {
            int m = g_idx[bn*MAXI + j];
            id[j] = m;
            float e = __expf(Srow[m] - mx) * iZ;
            a[j] = e; rs += e;
        }
    }
    float inv = 1.0f / (rs + 1e-6f);
    #pragma unroll
    for (int j = 0; j < MAXI; j++) {
        if (j < cnt) {
            float nr = a[j] * inv;
            g_nr[gid*MAXI + j] = nr;
            atomicAdd(&g_colsum[bc*NN + id[j]], nr);
            if (c == 0) {
                int p = atomicAdd(&g_colcnt[b*NN + id[j]], 1);
                g_colent[(b*NN + id[j])*NN + p] = (n << 5) | j;
            }
        }
    }
}

// ---------------- K5b: invert column sums ----------------------------------
__global__ void k5b_invcol(void) {
    int gid = blockIdx.x * blockDim.x + threadIdx.x;
    if (gid < BCN) g_invcol[gid] = 1.0f / (g_colsum[gid] + 1e-6f);
}

// ---------------- K6: out = norm_row @ norm_col^T (sparse x sparse) --------
__global__ void k6_final(float* __restrict__ out) {
    __shared__ float row[NN];
    const int bcn = blockIdx.x;
    const int bc = bcn >> 10, n = bcn & 1023;
    const int b = bc >> 3;
    const int tid = threadIdx.x;    // 128
    #pragma unroll
    for (int i = 0; i < 2; i++)
        ((float4*)row)[tid + i*128] = make_float4(0.f, 0.f, 0.f, 0.f);
    __syncthreads();
    const int bn = b*NN + n;
    const int cnt = g_cnt[bn];
    for (int j = 0; j < cnt; j++) {
        int k = g_idx[bn*MAXI + j];
        float ai = g_nr[(size_t)bcn*MAXI + j] * g_invcol[bc*NN + k];
        int cc = g_colcnt[b*NN + k];
        const int* ent = &g_colent[(b*NN + k)*NN];
        for (int e = tid; e < cc; e += 128) {
            int pk = ent[e];
            int m = pk >> 5, j2 = pk & 31;
            float ncv = g_nr[(bc*NN + m)*MAXI + j2];
            atomicAdd(&row[m], ai * ncv);
        }
    }
    __syncthreads();
    float* orow = out + (size_t)bcn * NN;
    #pragma unroll
    for (int i = 0; i < 2; i++)
        ((float4*)orow)[tid + i*128] = ((float4*)row)[tid + i*128];
}

// ---------------- launch ----------------------------------------------------
extern "C" void kernel_launch(void* const* d_in, const int* in_sizes, int n_in,
                              void* d_out, int out_size) {
    const float* x = (const float*)d_in[0];     // [4,1024,256]
    const float* W = (const float*)d_in[1];     // [256,4096]
    float* out = (float*)d_out;                 // [4,8,1024,1024]

    const int DYN = 98304;   // 3 stages x (16 KB A + 16 KB B)
    cudaFuncSetAttribute(k1_mma, cudaFuncAttributeMaxDynamicSharedMemorySize, DYN);
    cudaFuncSetAttribute(k2_mma, cudaFuncAttributeMaxDynamicSharedMemorySize, DYN);

    k0_splitx<<<(BN * DD) / 256, 256>>>(x);
    k0_splitW<<<dim3(128, 8), dim3(32, 8)>>>(W);
    k1_mma<<<dim3(32, 32), 256, DYN>>>();
    k2_mma<<<dim3(8, 8, 32), 256, DYN>>>();
    k3_stats<<<BN, 256>>>();
    k4_topk<<<BN / 8, 256>>>();
    k5_gather<<<BCN / 256, 256>>>();
    k5b_invcol<<<BCN / 256, 256>>>();
    k6_final<<<BCN, 128>>>(out);
}